// round 17
// baseline (speedup 1.0000x reference)
#include <cuda_runtime.h>
#include <cstdint>

#define NB 4
#define NL 2048
#define ND 1024
#define NH 16
#define NDH 64
#define NM (NB*NL)

// Scratch (allocation-free rule: __device__ globals)
static __device__ float g_x[(size_t)NM*ND];     // tf32-rounded x
static __device__ float g_w[(size_t)4*ND*ND];   // tf32-rounded Wq,Wk,Wv,Wo
static __device__ float g_q[(size_t)NM*ND];
static __device__ float g_k[(size_t)NM*ND];
static __device__ float g_v[(size_t)NM*ND];
static __device__ float g_att[(size_t)NM*ND];

__device__ __forceinline__ uint32_t f2tf(float x){
    uint32_t u; asm("cvt.rna.tf32.f32 %0, %1;" : "=r"(u) : "f"(x)); return u;
}
__device__ __forceinline__ float tfb(float x){ return __uint_as_float(f2tf(x)); }
__device__ __forceinline__ float4 tf4(float4 v){
    v.x = tfb(v.x); v.y = tfb(v.y); v.z = tfb(v.z); v.w = tfb(v.w); return v;
}

__device__ __forceinline__ void mma8(float* c,
    uint32_t a0, uint32_t a1, uint32_t a2, uint32_t a3,
    uint32_t b0, uint32_t b1)
{
    asm volatile(
      "mma.sync.aligned.m16n8k8.row.col.f32.tf32.tf32.f32 "
      "{%0,%1,%2,%3},{%4,%5,%6,%7},{%8,%9},{%0,%1,%2,%3};"
      : "+f"(c[0]), "+f"(c[1]), "+f"(c[2]), "+f"(c[3])
      : "r"(a0), "r"(a1), "r"(a2), "r"(a3), "r"(b0), "r"(b1));
}

__device__ __forceinline__ uint32_t smem_u32(const void* p){
    uint32_t a;
    asm("{ .reg .u64 t; cvta.to.shared.u64 t, %1; cvt.u32.u64 %0, t; }" : "=r"(a) : "l"(p));
    return a;
}
__device__ __forceinline__ void cpa16(uint32_t s, const void* g){
    asm volatile("cp.async.cg.shared.global [%0], [%1], 16;" :: "r"(s), "l"(g));
}
#define CP_COMMIT() asm volatile("cp.async.commit_group;" ::: "memory")
#define CP_WAIT0()  asm volatile("cp.async.wait_group 0;" ::: "memory")
#define CP_WAIT1()  asm volatile("cp.async.wait_group 1;" ::: "memory")

// ---------------------------------------------------------------------------
// Fused tf32 pre-round: z=0 -> x, z=1..4 -> Wq,Wk,Wv,Wo  (ONE launch)
// ---------------------------------------------------------------------------
__global__ void round_all_kernel(const float* __restrict__ x,
    const float* __restrict__ Wq, const float* __restrict__ Wk,
    const float* __restrict__ Wv, const float* __restrict__ Wo,
    float* __restrict__ gx, float* __restrict__ gw)
{
    const int z = blockIdx.y;
    const float* src; float* dst; int n4;
    if (z == 0){ src = x; dst = gx; n4 = NM*ND/4; }
    else {
        src = (z == 1) ? Wq : (z == 2) ? Wk : (z == 3) ? Wv : Wo;
        dst = gw + (size_t)(z-1)*ND*ND;
        n4  = ND*ND/4;
    }
    for (int i = blockIdx.x*blockDim.x + threadIdx.x; i < n4; i += gridDim.x*blockDim.x){
        float4 v = reinterpret_cast<const float4*>(src)[i];
        reinterpret_cast<float4*>(dst)[i] = tf4(v);
    }
}

// ---------------------------------------------------------------------------
// GEMM: C[8192,1024] = A @ W + bias. Block 128x128x32, 4 warps (2x1 of 64x64
// warp tiles). Inputs pre-rounded tf32 -> pure cp.async, THREE-stage pipeline
// (wait_group 1 keeps one tile in flight while computing). QKV: z selects
// bias/output, epilogue permutes to [B,H,L,Dh] + re-rounds.
// ---------------------------------------------------------------------------
constexpr int AS_STRIDE = 36;
constexpr int BS_STRIDE = 136;
constexpr int AS_SZ = 128*AS_STRIDE;            // 4608 floats
constexpr int BS_SZ = 32*BS_STRIDE;             // 4352 floats
constexpr int ST_SZ = AS_SZ + BS_SZ;            // 8960 floats per stage
constexpr int GEMM_SMEM = 3*ST_SZ*4;            // 107520 B -> 2 CTAs/SM

template<bool QKV>
__global__ void __launch_bounds__(128) gemm_kernel(
    const float* __restrict__ A, const float* __restrict__ Wall,
    const float* __restrict__ bz0, const float* __restrict__ bz1, const float* __restrict__ bz2,
    float* __restrict__ Cz0, float* __restrict__ Cz1, float* __restrict__ Cz2)
{
    extern __shared__ float sm[];
    const uint32_t sbase = smem_u32(sm);

    const int z = QKV ? blockIdx.z : 3;
    const float* W    = Wall + (size_t)z*ND*ND;
    const float* bias = QKV ? ((z == 0) ? bz0 : (z == 1) ? bz1 : bz2) : bz0;
    float* C          = QKV ? ((z == 0) ? Cz0 : (z == 1) ? Cz1 : Cz2) : Cz0;

    const int tid  = threadIdx.x;
    const int lane = tid & 31;
    const int warp = tid >> 5;
    const int wm   = warp >> 1;
    const int wn   = warp & 1;
    const int bm0  = blockIdx.y * 128;
    const int bn0  = blockIdx.x * 128;

    float acc[4][8][4];
    #pragma unroll
    for (int mt=0; mt<4; mt++)
      #pragma unroll
      for (int nt=0; nt<8; nt++)
        #pragma unroll
        for (int i=0; i<4; i++) acc[mt][nt][i] = 0.f;

    const int arow = tid >> 3, ac4 = (tid & 7) * 4;
    const int brow = tid >> 5, bc4 = (tid & 31) * 4;

    auto load_tile = [&](int kt, int st){
        const uint32_t sa = sbase + (uint32_t)(st*ST_SZ*4);
        const uint32_t sb = sa + (uint32_t)(AS_SZ*4);
        #pragma unroll
        for (int p=0; p<8; p++){
            const int row = p*16 + arow;
            cpa16(sa + (uint32_t)((row*AS_STRIDE + ac4)*4),
                  A + (size_t)(bm0 + row)*ND + kt*32 + ac4);
        }
        #pragma unroll
        for (int p=0; p<8; p++){
            const int row = p*4 + brow;
            cpa16(sb + (uint32_t)((row*BS_STRIDE + bc4)*4),
                  W + (size_t)(kt*32 + row)*ND + bn0 + bc4);
        }
    };

    load_tile(0, 0); CP_COMMIT();
    load_tile(1, 1); CP_COMMIT();

    const int NKT = ND/32;   // 32
    int st = 0;
    for (int kt=0; kt<NKT; ++kt){
        if (kt+1 < NKT) { CP_WAIT1(); } else { CP_WAIT0(); }   // tile kt arrived
        __syncthreads();                                        // stage (kt+2)%3 free
        if (kt+2 < NKT){
            int st2 = st + 2; if (st2 >= 3) st2 -= 3;
            load_tile(kt+2, st2); CP_COMMIT();
        }

        const float* a_ = sm + st*ST_SZ;
        const float* b_ = a_ + AS_SZ;

        #pragma unroll
        for (int ks=0; ks<4; ks++){
            const int k0 = ks*8 + (lane & 3);
            uint32_t af[4][4];
            #pragma unroll
            for (int mt=0; mt<4; mt++){
                const int r0 = wm*64 + mt*16 + (lane >> 2);
                af[mt][0] = __float_as_uint(a_[ r0   *AS_STRIDE + k0    ]);
                af[mt][1] = __float_as_uint(a_[(r0+8)*AS_STRIDE + k0    ]);
                af[mt][2] = __float_as_uint(a_[ r0   *AS_STRIDE + k0 + 4]);
                af[mt][3] = __float_as_uint(a_[(r0+8)*AS_STRIDE + k0 + 4]);
            }
            #pragma unroll
            for (int nt=0; nt<8; nt++){
                const int n0 = wn*64 + nt*8 + (lane >> 2);
                const uint32_t bb0 = __float_as_uint(b_[ k0   *BS_STRIDE + n0]);
                const uint32_t bb1 = __float_as_uint(b_[(k0+4)*BS_STRIDE + n0]);
                #pragma unroll
                for (int mt=0; mt<4; mt++)
                    mma8(acc[mt][nt], af[mt][0],af[mt][1],af[mt][2],af[mt][3], bb0, bb1);
            }
        }
        if (++st >= 3) st -= 3;
    }

    #pragma unroll
    for (int mt=0; mt<4; mt++){
        const int rbase = bm0 + wm*64 + mt*16 + (lane >> 2);
        #pragma unroll
        for (int nt=0; nt<8; nt++){
            const int cbase = bn0 + wn*64 + nt*8 + 2*(lane & 3);
            #pragma unroll
            for (int i=0; i<4; i++){
                const int r = rbase + (i>>1)*8;
                const int c = cbase + (i&1);
                const float v = acc[mt][nt][i] + bias[c];
                if (QKV){
                    const size_t idx = (((size_t)(r >> 11)*NH + (c >> 6))*NL + (r & (NL-1)))*NDH + (c & 63);
                    C[idx] = tfb(v);
                } else {
                    C[(size_t)r*ND + c] = v;
                }
            }
        }
    }
}

// ---------------------------------------------------------------------------
// FlashAttention-2, causal. BM=64 q rows/CTA, BN=64 keys/step, 4 warps x 16
// rows, 128 threads, 3 CTAs/SM. K double-buffered; V single-buffered.
// blockIdx.x REVERSED -> heaviest (longest-KV) tiles scheduled first.
// ---------------------------------------------------------------------------
constexpr int FQS = 68;
constexpr int FKS = 68;
constexpr int FVS = 72;
constexpr int FK_OFF = 64*FQS;
constexpr int FV_OFF = FK_OFF + 2*64*FKS;
constexpr int FL_SMEM = (FV_OFF + 64*FVS)*4;    // 70656 B -> 3 CTAs/SM

__global__ void __launch_bounds__(128, 3) flash_kernel(
    const float* __restrict__ Qg, const float* __restrict__ Kg,
    const float* __restrict__ Vg, float* __restrict__ Og)
{
    extern __shared__ float sm[];
    float* sQ = sm;
    float* sKb[2] = { sm + FK_OFF, sm + FK_OFF + 64*FKS };
    float* sV = sm + FV_OFF;
    const uint32_t sbase = smem_u32(sm);

    const int tid  = threadIdx.x;
    const int lane = tid & 31;
    const int warp = tid >> 5;
    const int bh   = blockIdx.y;
    const int q0   = (gridDim.x - 1 - blockIdx.x) * 64;   // heavy tiles first

    const float* Qb = Qg + (size_t)bh*NL*NDH;
    const float* Kb = Kg + (size_t)bh*NL*NDH;
    const float* Vb = Vg + (size_t)bh*NL*NDH;

    const int r_ = tid >> 4;
    const int c4 = (tid & 15) * 4;

    #pragma unroll
    for (int p=0; p<8; p++){
        const int row = p*8 + r_;
        cpa16(sbase + (uint32_t)((row*FQS + c4)*4), Qb + (size_t)(q0 + row)*NDH + c4);
    }
    CP_COMMIT();

    auto load_k = [&](int t, int buf){
        const uint32_t kb = sbase + (uint32_t)((FK_OFF + buf*64*FKS)*4);
        #pragma unroll
        for (int p=0; p<8; p++){
            const int row = p*8 + r_;
            cpa16(kb + (uint32_t)((row*FKS + c4)*4), Kb + (size_t)(t*64 + row)*NDH + c4);
        }
    };
    auto load_v = [&](int t){
        const uint32_t vb = sbase + (uint32_t)(FV_OFF*4);
        #pragma unroll
        for (int p=0; p<8; p++){
            const int row = p*8 + r_;
            cpa16(vb + (uint32_t)((row*FVS + c4)*4), Vb + (size_t)(t*64 + row)*NDH + c4);
        }
    };

    CP_WAIT0();
    __syncthreads();

    uint32_t qf[8][4];
    const int rloc = warp*16 + (lane >> 2);
    #pragma unroll
    for (int ks=0; ks<8; ks++){
        const int k0 = ks*8 + (lane & 3);
        qf[ks][0] = __float_as_uint(sQ[ rloc   *FQS + k0    ]);
        qf[ks][1] = __float_as_uint(sQ[(rloc+8)*FQS + k0    ]);
        qf[ks][2] = __float_as_uint(sQ[ rloc   *FQS + k0 + 4]);
        qf[ks][3] = __float_as_uint(sQ[(rloc+8)*FQS + k0 + 4]);
    }

    load_k(0, 0); CP_COMMIT();

    float o[8][4];
    #pragma unroll
    for (int nt=0; nt<8; nt++)
      #pragma unroll
      for (int i=0; i<4; i++) o[nt][i] = 0.f;

    float mi0 = -1e30f, mi1 = -1e30f, li0 = 0.f, li1 = 0.f;
    const int rg0 = q0 + rloc;
    const int ntile = q0/64 + 1;

    for (int t=0; t<ntile; ++t){
        const int buf = t & 1;
        CP_WAIT0();
        __syncthreads();

        load_v(t); CP_COMMIT();

        const float* K_ = sKb[buf];

        float sc[8][4];
        #pragma unroll
        for (int nt=0; nt<8; nt++)
          #pragma unroll
          for (int i=0; i<4; i++) sc[nt][i] = 0.f;

        #pragma unroll
        for (int ks=0; ks<8; ks++){
            const int k0 = ks*8 + (lane & 3);
            #pragma unroll
            for (int nt=0; nt<8; nt++){
                const int n0 = nt*8 + (lane >> 2);
                const uint32_t bb0 = __float_as_uint(K_[n0*FKS + k0    ]);
                const uint32_t bb1 = __float_as_uint(K_[n0*FKS + k0 + 4]);
                mma8(sc[nt], qf[ks][0],qf[ks][1],qf[ks][2],qf[ks][3], bb0, bb1);
            }
        }

        const bool hasNext = (t+1 < ntile);
        if (hasNext){ load_k(t+1, buf^1); CP_COMMIT(); }

        const int kv0 = t*64;
        const bool diagTile = (t == ntile-1);
        #pragma unroll
        for (int nt=0; nt<8; nt++){
            const int c0 = kv0 + nt*8 + 2*(lane & 3);
            #pragma unroll
            for (int i=0; i<4; i++){
                float s = sc[nt][i] * 0.125f;
                if (diagTile){
                    const int cc = c0 + (i & 1);
                    const int rr = rg0 + ((i >> 1) * 8);
                    if (cc > rr) s = -1e30f;
                }
                sc[nt][i] = s;
            }
        }

        float mt0 = -1e30f, mt1 = -1e30f;
        #pragma unroll
        for (int nt=0; nt<8; nt++){
            mt0 = fmaxf(mt0, fmaxf(sc[nt][0], sc[nt][1]));
            mt1 = fmaxf(mt1, fmaxf(sc[nt][2], sc[nt][3]));
        }
        mt0 = fmaxf(mt0, __shfl_xor_sync(0xffffffffu, mt0, 1));
        mt0 = fmaxf(mt0, __shfl_xor_sync(0xffffffffu, mt0, 2));
        mt1 = fmaxf(mt1, __shfl_xor_sync(0xffffffffu, mt1, 1));
        mt1 = fmaxf(mt1, __shfl_xor_sync(0xffffffffu, mt1, 2));

        const float mn0 = fmaxf(mi0, mt0);
        const float mn1 = fmaxf(mi1, mt1);
        const float sf0 = __expf(mi0 - mn0);
        const float sf1 = __expf(mi1 - mn1);

        float sum0 = 0.f, sum1 = 0.f;
        #pragma unroll
        for (int nt=0; nt<8; nt++){
            sc[nt][0] = __expf(sc[nt][0] - mn0); sum0 += sc[nt][0];
            sc[nt][1] = __expf(sc[nt][1] - mn0); sum0 += sc[nt][1];
            sc[nt][2] = __expf(sc[nt][2] - mn1); sum1 += sc[nt][2];
            sc[nt][3] = __expf(sc[nt][3] - mn1); sum1 += sc[nt][3];
        }
        sum0 += __shfl_xor_sync(0xffffffffu, sum0, 1);
        sum0 += __shfl_xor_sync(0xffffffffu, sum0, 2);
        sum1 += __shfl_xor_sync(0xffffffffu, sum1, 1);
        sum1 += __shfl_xor_sync(0xffffffffu, sum1, 2);

        li0 = li0*sf0 + sum0;  li1 = li1*sf1 + sum1;
        mi0 = mn0;             mi1 = mn1;

        #pragma unroll
        for (int nt=0; nt<8; nt++){
            o[nt][0] *= sf0; o[nt][1] *= sf0;
            o[nt][2] *= sf1; o[nt][3] *= sf1;
        }

        if (hasNext) { CP_WAIT1(); } else { CP_WAIT0(); }
        __syncthreads();

        #pragma unroll
        for (int nt=0; nt<8; nt++){
            const int c0 = nt*8 + 2*(lane & 3);
            sQ[ rloc   *FQS + c0    ] = __uint_as_float(f2tf(sc[nt][0]));
            sQ[ rloc   *FQS + c0 + 1] = __uint_as_float(f2tf(sc[nt][1]));
            sQ[(rloc+8)*FQS + c0    ] = __uint_as_float(f2tf(sc[nt][2]));
            sQ[(rloc+8)*FQS + c0 + 1] = __uint_as_float(f2tf(sc[nt][3]));
        }
        __syncwarp();

        #pragma unroll
        for (int ks=0; ks<8; ks++){
            const int k0 = ks*8 + (lane & 3);
            const uint32_t a0 = __float_as_uint(sQ[ rloc   *FQS + k0    ]);
            const uint32_t a1 = __float_as_uint(sQ[(rloc+8)*FQS + k0    ]);
            const uint32_t a2 = __float_as_uint(sQ[ rloc   *FQS + k0 + 4]);
            const uint32_t a3 = __float_as_uint(sQ[(rloc+8)*FQS + k0 + 4]);
            #pragma unroll
            for (int nt=0; nt<8; nt++){
                const int n0 = nt*8 + (lane >> 2);
                const uint32_t bb0 = __float_as_uint(sV[ k0   *FVS + n0]);
                const uint32_t bb1 = __float_as_uint(sV[(k0+4)*FVS + n0]);
                mma8(o[nt], a0, a1, a2, a3, bb0, bb1);
            }
        }
    }

    const float inv0 = 1.f / li0;
    const float inv1 = 1.f / li1;
    const int b = bh >> 4;
    const int h = bh & 15;
    #pragma unroll
    for (int nt=0; nt<8; nt++){
        const int d0 = nt*8 + 2*(lane & 3);
        #pragma unroll
        for (int i=0; i<4; i++){
            const int rr = rg0 + ((i >> 1) * 8);
            const int dh = d0 + (i & 1);
            const float v = o[nt][i] * ((i >= 2) ? inv1 : inv0);
            Og[((size_t)b*NL + rr)*ND + h*NDH + dh] = tfb(v);
        }
    }
}

// ---------------------------------------------------------------------------
extern "C" void kernel_launch(void* const* d_in, const int* in_sizes, int n_in,
                              void* d_out, int out_size)
{
    (void)in_sizes; (void)n_in; (void)out_size;
    const float* x  = (const float*)d_in[0];
    const float* Wq = (const float*)d_in[1];
    const float* bq = (const float*)d_in[2];
    const float* Wk = (const float*)d_in[3];
    const float* bk = (const float*)d_in[4];
    const float* Wv = (const float*)d_in[5];
    const float* bv = (const float*)d_in[6];
    const float* Wo = (const float*)d_in[7];
    const float* bo = (const float*)d_in[8];
    float* out = (float*)d_out;

    float *gx, *gw, *gq, *gk, *gv, *gatt;
    cudaGetSymbolAddress((void**)&gx,   g_x);
    cudaGetSymbolAddress((void**)&gw,   g_w);
    cudaGetSymbolAddress((void**)&gq,   g_q);
    cudaGetSymbolAddress((void**)&gk,   g_k);
    cudaGetSymbolAddress((void**)&gv,   g_v);
    cudaGetSymbolAddress((void**)&gatt, g_att);

    cudaFuncSetAttribute(gemm_kernel<true>,
        cudaFuncAttributeMaxDynamicSharedMemorySize, GEMM_SMEM);
    cudaFuncSetAttribute(gemm_kernel<false>,
        cudaFuncAttributeMaxDynamicSharedMemorySize, GEMM_SMEM);
    cudaFuncSetAttribute(flash_kernel,
        cudaFuncAttributeMaxDynamicSharedMemorySize, FL_SMEM);

    // 1) fused pre-round of x + all weights
    dim3 rg(1024, 5);
    round_all_kernel<<<rg, 256>>>(x, Wq, Wk, Wv, Wo, gx, gw);

    // 2) fused QKV projection (3-stage pipeline)
    dim3 gqkv(ND/128, NM/128, 3);
    gemm_kernel<true><<<gqkv, 128, GEMM_SMEM>>>(
        gx, gw, bq, bk, bv, gq, gk, gv);

    // 3) flash attention (causal), heavy tiles first
    dim3 gf(NL/64, NB*NH);
    flash_kernel<<<gf, 128, FL_SMEM>>>(gq, gk, gv, gatt);

    // 4) output projection
    dim3 gg(ND/128, NM/128);
    gemm_kernel<false><<<gg, 128, GEMM_SMEM>>>(
        gatt, gw, bo, nullptr, nullptr, out, nullptr, nullptr);
}